// round 6
// baseline (speedup 1.0000x reference)
#include <cuda_runtime.h>
#include <cuda_bf16.h>
#include <math_constants.h>
#include <cstdint>

#define BB 64
#define SS 4096
#define DD 256
#define ROWS 16                       // rows per tile
#define TILES 8                       // tiles per CTA -> 128 rows per CTA
#define NCC (SS / (ROWS * TILES))     // 32 chunks per batch
#define TILE_B (ROWS * DD * 4)        // 16 KB

// Scratch (allocation-free: __device__ globals; zero-init at module load)
__device__ float g_pm[BB * NCC];           // chunk running max
__device__ float g_pl[BB * NCC];           // chunk exp-sum
__device__ float g_pa[BB * NCC * DD];      // weighted partials (2 MB)
__device__ int   g_cnt[BB];                // arrival counters (reset by last CTA)

__device__ __forceinline__ uint32_t smem_u32(const void* p) {
    uint32_t a;
    asm("{ .reg .u64 t; cvta.to.shared.u64 t, %1; cvt.u32.u64 %0, t; }"
        : "=r"(a) : "l"(p));
    return a;
}

__device__ __forceinline__ void mbar_wait(uint32_t mbar, uint32_t parity) {
    asm volatile(
        "{\n\t"
        ".reg .pred P;\n\t"
        "WAIT_%=:\n\t"
        "mbarrier.try_wait.parity.acquire.cta.shared::cta.b64 P, [%0], %1, 0x989680;\n\t"
        "@P bra.uni DONE_%=;\n\t"
        "bra.uni WAIT_%=;\n\t"
        "DONE_%=:\n\t"
        "}" :: "r"(mbar), "r"(parity) : "memory");
}

__device__ __forceinline__ void tma_tile(uint32_t mb, uint32_t sdst, const float* src) {
    asm volatile("mbarrier.arrive.expect_tx.shared.b64 _, [%0], %1;"
                 :: "r"(mb), "r"((uint32_t)TILE_B) : "memory");
    asm volatile(
        "cp.async.bulk.shared::cta.global.mbarrier::complete_tx::bytes "
        "[%0], [%1], %2, [%3];"
        :: "r"(sdst), "l"(src), "r"((uint32_t)TILE_B), "r"(mb) : "memory");
}

// ---------------------------------------------------------------------------
// Single fused kernel: grid = BB * NCC = 2048 CTAs, 256 threads.
//   Phase A: stream 8 x 16-row tiles through a 2-deep TMA pipeline with an
//            online-softmax accumulator; write per-chunk partials.
//   Phase B: the LAST CTA to finish for batch b (threadfence-reduction
//            pattern) combines the 32 chunk partials and writes out[:, b].
// ---------------------------------------------------------------------------
__global__ __launch_bounds__(256) void ta_fused_kernel(
    const float* __restrict__ enc,   // [B, S, D]
    const float* __restrict__ Ww,    // [1, D]
    const float* __restrict__ ut,    // [1, 1]
    float* __restrict__ out)         // [D, B]
{
    __shared__ __align__(128) float sx[2][ROWS][DD];   // 2 x 16 KB
    __shared__ float sraw[ROWS];
    __shared__ float wsc[NCC];
    __shared__ int   s_last;
    __shared__ __align__(8) unsigned long long mbar[2];

    const int blk  = blockIdx.x;
    const int b    = blk >> 5;        // / NCC
    const int cc   = blk & (NCC - 1);
    const int tid  = threadIdx.x;
    const int w    = tid >> 5;
    const int lane = tid & 31;

    const uint32_t mb0 = smem_u32(&mbar[0]);
    const uint32_t mb1 = smem_u32(&mbar[1]);
    const uint32_t sd0 = smem_u32(&sx[0][0][0]);
    const uint32_t sd1 = smem_u32(&sx[1][0][0]);

    if (tid == 0) {
        asm volatile("mbarrier.init.shared.b64 [%0], 1;" :: "r"(mb0) : "memory");
        asm volatile("mbarrier.init.shared.b64 [%0], 1;" :: "r"(mb1) : "memory");
    }
    __syncthreads();

    const float* src0 = enc + ((size_t)b * SS + (size_t)cc * ROWS * TILES) * DD;

    if (tid == 0) {
        tma_tile(mb0, sd0, src0);
        tma_tile(mb1, sd1, src0 + ROWS * DD);
    }

    const float u = ut[0];
    const float4 w0 = reinterpret_cast<const float4*>(Ww)[lane];
    const float4 w1 = reinterpret_cast<const float4*>(Ww)[lane + 32];

    float acc = 0.f;                // per-thread column d = tid
    float M_r = -1e30f, L_r = 0.f;  // replicated across all threads

    #pragma unroll
    for (int k = 0; k < TILES; k++) {
        const int buf = k & 1;
        const uint32_t mb = buf ? mb1 : mb0;
        mbar_wait(mb, (k >> 1) & 1);

        // ---- scores: warp w handles rows w and w+8 ----
        const float4* t4 = reinterpret_cast<const float4*>(&sx[buf][0][0]);
        const float4 a00 = t4[w * 64 + lane];
        const float4 a01 = t4[w * 64 + lane + 32];
        const float4 a10 = t4[(w + 8) * 64 + lane];
        const float4 a11 = t4[(w + 8) * 64 + lane + 32];

        float p0x = a00.x * w0.x, p0y = a00.y * w0.y;
        float p1x = a10.x * w0.x, p1y = a10.y * w0.y;
        p0x = fmaf(a00.z, w0.z, p0x); p0y = fmaf(a00.w, w0.w, p0y);
        p1x = fmaf(a10.z, w0.z, p1x); p1y = fmaf(a10.w, w0.w, p1y);
        p0x = fmaf(a01.x, w1.x, p0x); p0y = fmaf(a01.y, w1.y, p0y);
        p1x = fmaf(a11.x, w1.x, p1x); p1y = fmaf(a11.y, w1.y, p1y);
        p0x = fmaf(a01.z, w1.z, p0x); p0y = fmaf(a01.w, w1.w, p0y);
        p1x = fmaf(a11.z, w1.z, p1x); p1y = fmaf(a11.w, w1.w, p1y);
        float p0 = p0x + p0y;
        float p1 = p1x + p1y;
        #pragma unroll
        for (int off = 16; off > 0; off >>= 1) {
            p0 += __shfl_xor_sync(0xffffffffu, p0, off);
            p1 += __shfl_xor_sync(0xffffffffu, p1, off);
        }
        if (lane == 0) { sraw[w] = p0; sraw[w + 8] = p1; }
        __syncthreads();

        // ---- online softmax update: EVERY warp redundantly (identical) ----
        // lanes 16-31 mirror lanes 0-15; xor-reduce over 16 converges all.
        const float v = u * sraw[lane & 15];
        float m = v;
        #pragma unroll
        for (int off = 8; off > 0; off >>= 1)
            m = fmaxf(m, __shfl_xor_sync(0xffffffffu, m, off));
        const float newM   = fmaxf(M_r, m);
        const float sc_old = __expf(M_r - newM);
        const float e      = __expf(v - newM);   // lane s holds e for row s&15
        float l = e;
        #pragma unroll
        for (int off = 8; off > 0; off >>= 1)
            l += __shfl_xor_sync(0xffffffffu, l, off);
        L_r = L_r * sc_old + l;
        M_r = newM;

        // ---- rescale + accumulate (e broadcast via shuffle, no smem) ----
        acc *= sc_old;
        #pragma unroll
        for (int s = 0; s < ROWS; s++) {
            const float es = __shfl_sync(0xffffffffu, e, s);
            acc = fmaf(es, sx[buf][s][tid], acc);
        }
        __syncthreads();   // all threads done with sx[buf] before refill

        if (tid == 0 && k + 2 < TILES)
            tma_tile(mb, buf ? sd1 : sd0, src0 + (size_t)(k + 2) * ROWS * DD);
    }

    // ---- publish partials ----
    g_pa[((size_t)(b * NCC + cc)) * DD + tid] = acc;
    if (tid == 0) {
        g_pm[b * NCC + cc] = M_r;
        g_pl[b * NCC + cc] = L_r;
    }

    // ---- threadfence reduction: last CTA of batch b combines ----
    __threadfence();
    if (tid == 0) {
        const int old = atomicAdd(&g_cnt[b], 1);
        s_last = (old == NCC - 1);
    }
    __syncthreads();
    if (!s_last) return;

    if (tid == 0) g_cnt[b] = 0;   // reset for next graph replay
    __threadfence();

    // warp 0: global M, L and normalized chunk weights (L2 reads, bypass L1)
    if (tid < NCC) {
        const float m = __ldcg(&g_pm[b * NCC + tid]);
        const float l = __ldcg(&g_pl[b * NCC + tid]);
        float M = m;
        #pragma unroll
        for (int off = 16; off > 0; off >>= 1)
            M = fmaxf(M, __shfl_xor_sync(0xffffffffu, M, off));
        const float ee = __expf(m - M);
        float L = ee * l;
        #pragma unroll
        for (int off = 16; off > 0; off >>= 1)
            L += __shfl_xor_sync(0xffffffffu, L, off);
        wsc[tid] = ee / L;
    }
    __syncthreads();

    // thread d = tid: out[d, b] = sum_c wsc[c] * pa[b][c][d]
    float o0 = 0.f, o1 = 0.f;
    #pragma unroll
    for (int c = 0; c < NCC; c += 2) {
        o0 = fmaf(wsc[c],     __ldcg(&g_pa[((size_t)(b * NCC + c))     * DD + tid]), o0);
        o1 = fmaf(wsc[c + 1], __ldcg(&g_pa[((size_t)(b * NCC + c + 1)) * DD + tid]), o1);
    }
    out[tid * BB + b] = o0 + o1;
}

extern "C" void kernel_launch(void* const* d_in, const int* in_sizes, int n_in,
                              void* d_out, int out_size)
{
    const float* enc = (const float*)d_in[0];   // [B, S, D]
    const float* Ww  = (const float*)d_in[1];   // [1, D]
    // d_in[2] = We_b : scalar bias is softmax-invariant, dropped
    const float* ut  = (const float*)d_in[3];   // [1, 1]
    float* out = (float*)d_out;                 // [D, B]

    ta_fused_kernel<<<BB * NCC, 256>>>(enc, Ww, ut, out);
}